// round 2
// baseline (speedup 1.0000x reference)
#include <cuda_runtime.h>
#include <cuda_bf16.h>
#include <cstdint>

#define BATCH 64
#define ISZ   64
#define SEQ   4096
#define ESZ   64
#define TS    256   // s-values per block (1 per thread)

// Packed fp32x2 helpers (Blackwell sm_100+; ptxas will not auto-fuse these)
__device__ __forceinline__ unsigned long long pk2(float a, float b) {
    unsigned long long r;
    asm("mov.b64 %0, {%1, %2};" : "=l"(r) : "f"(a), "f"(b));
    return r;
}
__device__ __forceinline__ unsigned long long fma2(unsigned long long a,
                                                   unsigned long long b,
                                                   unsigned long long c) {
    unsigned long long d;
    asm("fma.rn.f32x2 %0, %1, %2, %3;" : "=l"(d) : "l"(a), "l"(b), "l"(c));
    return d;
}

__global__ __launch_bounds__(TS)
void embed_f32x2_kernel(const float* __restrict__ in,    // [B, I, S]
                        const float* __restrict__ emb,   // [I, E]
                        float* __restrict__ out) {       // [B, S, E]
    // Embedding staged in SMEM as packed f32x2 pairs:
    // semb[i*32 + j] = (emb[i][2j], emb[i][2j+1])
    __shared__ unsigned long long semb[ISZ * ESZ / 2];   // 16 KB

    const int tid = threadIdx.x;

    // Cooperative 16B-vector load of the 64x64 embedding
    {
        const float4* src = reinterpret_cast<const float4*>(emb);
        float4* dst = reinterpret_cast<float4*>(semb);
        #pragma unroll
        for (int k = tid; k < ISZ * ESZ / 4; k += TS) dst[k] = src[k];
    }
    __syncthreads();

    const int s = blockIdx.x * TS + tid;
    const int b = blockIdx.y;
    const float* ip = in + (size_t)b * ISZ * SEQ + s;

    unsigned long long acc[ESZ / 2];
    #pragma unroll
    for (int j = 0; j < ESZ / 2; j++) acc[j] = 0ull;

    // Main loop over the contraction dim. Unroll-8 batches 8 independent LDGs
    // up front (MLP ~ 8) so DRAM latency hides behind the f32x2 FMA stream.
    #pragma unroll 8
    for (int i = 0; i < ISZ; i++) {
        const float x = __ldcs(ip + (size_t)i * SEQ);          // coalesced, no reuse
        const unsigned long long xx = pk2(x, x);
        const ulonglong2* e2 = reinterpret_cast<const ulonglong2*>(semb + i * (ESZ / 2));
        #pragma unroll
        for (int j = 0; j < ESZ / 4; j++) {
            ulonglong2 v = e2[j];                               // LDS.128, full broadcast
            acc[2 * j]     = fma2(v.x, xx, acc[2 * j]);
            acc[2 * j + 1] = fma2(v.y, xx, acc[2 * j + 1]);
        }
    }

    // Each thread writes its contiguous 256 B of out[b, s, :] with 16 B
    // streaming stores (written once, never re-read).
    float* op = out + ((size_t)b * SEQ + s) * ESZ;
    #pragma unroll
    for (int j = 0; j < ESZ / 4; j++) {
        float4 v;
        unsigned long long lo = acc[2 * j];
        unsigned long long hi = acc[2 * j + 1];
        asm("mov.b64 {%0, %1}, %2;" : "=f"(v.x), "=f"(v.y) : "l"(lo));
        asm("mov.b64 {%0, %1}, %2;" : "=f"(v.z), "=f"(v.w) : "l"(hi));
        __stcs(reinterpret_cast<float4*>(op) + j, v);
    }
}

extern "C" void kernel_launch(void* const* d_in, const int* in_sizes, int n_in,
                              void* d_out, int out_size) {
    const float* in  = (const float*)d_in[0];   // inputs [64, 64, 4096] fp32
    const float* emb = (const float*)d_in[1];   // embedding [64, 64] fp32
    float* out = (float*)d_out;                 // [64, 4096, 64] fp32

    dim3 grid(SEQ / TS, BATCH);  // (16, 64) = 1024 blocks
    embed_f32x2_kernel<<<grid, TS>>>(in, emb, out);
}